// round 2
// baseline (speedup 1.0000x reference)
#include <cuda_runtime.h>

// Problem constants
#define B_   512
#define T_   100
#define L_   256
#define D_   128
#define NPT  511          // nodes per tree = 2*L-1
#define TL_  25600        // T * L
#define BT_  51200        // B * T

typedef unsigned long long ull;

// ---------------------------------------------------------------------------
// Scratch (device globals: no allocation allowed)
// ---------------------------------------------------------------------------
__device__ float g_H[2][(size_t)TL_ * D_];   // ping-pong hidden state per level
__device__ float g_C[2][(size_t)TL_ * D_];   // ping-pong cell state per level
__device__ float g_Wt[256 * 512];            // W^T: [k=0..255][n=0..511], k = [x|h]
__device__ float g_bias[512];                // b_ih + b_hh
__device__ int   g_leaf[BT_];                // leaf index per (b,t), -1 if inactive

// ---------------------------------------------------------------------------
// Helpers
// ---------------------------------------------------------------------------
__device__ __forceinline__ void ffma2(ull &acc, ull a, ull b) {
    asm("fma.rn.f32x2 %0, %1, %2, %0;" : "+l"(acc) : "l"(a), "l"(b));
}
__device__ __forceinline__ ull dup2(float z) {
    ull r; asm("mov.b64 %0, {%1, %1};" : "=l"(r) : "f"(z)); return r;
}
__device__ __forceinline__ float2 unpk(ull v) {
    float2 r; asm("mov.b64 {%0, %1}, %2;" : "=f"(r.x), "=f"(r.y) : "l"(v)); return r;
}
__device__ __forceinline__ ull pk2(float x, float y) {
    ull r; asm("mov.b64 %0, {%1, %2};" : "=l"(r) : "f"(x), "f"(y)); return r;
}
__device__ __forceinline__ float sigf(float x) {
    return __fdividef(1.f, 1.f + __expf(-x));
}
__device__ __forceinline__ float tanhf_(float x) {
    float e = __expf(2.f * x);
    return 1.f - __fdividef(2.f, e + 1.f);
}
__device__ __forceinline__ void cpa16(float* s, const float* g) {
    unsigned sa = (unsigned)__cvta_generic_to_shared(s);
    asm volatile("cp.async.cg.shared.global [%0], [%1], 16;" :: "r"(sa), "l"(g));
}
#define CP_COMMIT() asm volatile("cp.async.commit_group;")
#define CP_WAIT0()  asm volatile("cp.async.wait_group 0;")

// ---------------------------------------------------------------------------
// Prep: transpose/concat weights to Wt[k][n], fuse biases
// ---------------------------------------------------------------------------
__global__ void prep_kernel(const float* __restrict__ w_ih, const float* __restrict__ w_hh,
                            const float* __restrict__ b_ih, const float* __restrict__ b_hh) {
    int idx = blockIdx.x * blockDim.x + threadIdx.x;
    if (idx < 256 * 512) {
        int d = idx >> 9;
        int n = idx & 511;
        g_Wt[idx] = (d < 128) ? w_ih[n * 128 + d] : w_hh[n * 128 + (d - 128)];
    }
    if (idx < 512) g_bias[idx] = b_ih[idx] + b_hh[idx];
}

// ---------------------------------------------------------------------------
// Argmax over the one-hot cross row: one warp per (b,t)
// ---------------------------------------------------------------------------
__global__ void leaf_kernel(const float* __restrict__ cross) {
    int gw   = (blockIdx.x * blockDim.x + threadIdx.x) >> 5;
    int lane = threadIdx.x & 31;
    if (gw >= BT_) return;
    const float* row = cross + (size_t)gw * L_;
    float best = row[lane];
    int   bi   = lane;
    #pragma unroll
    for (int i = lane + 32; i < L_; i += 32) {
        float v = row[i];
        if (v > best) { best = v; bi = i; }
    }
    #pragma unroll
    for (int off = 16; off; off >>= 1) {
        float ob = __shfl_down_sync(0xffffffffu, best, off);
        int   oi = __shfl_down_sync(0xffffffffu, bi,   off);
        if (ob > best || (ob == best && oi < bi)) { best = ob; bi = oi; }
    }
    if (lane == 0) g_leaf[gw] = (best > 0.f) ? bi : -1;
}

// ---------------------------------------------------------------------------
// Small levels 0..5 fused: one block per tree, H/C held in smem across levels.
// 512 threads: tx = tid&63 owns cols {2tx,2tx+1} per gate quadrant,
// ty = tid>>6 handles rows r = ty + i*8 (i < 4, M up to 32).
// W double-buffered via cp.async. Level-5 result -> g_H[1]/g_C[1].
// ---------------------------------------------------------------------------
#define SZS 34   // Z stride (34 mod 32 == 2 -> 2-way max store conflict)

__global__ void __launch_bounds__(512, 1)
lstm_small_kernel(const float* __restrict__ emb) {
    extern __shared__ float smem[];
    float* Zs = smem;                 // [256][SZS] = 8704
    float* Wb = Zs + 256 * SZS;       // [2][16][512] = 16384
    float* Hb = Wb + 16384;           // [2][32*128] = 8192
    float* Cb = Hb + 8192;            // [2][32*128] = 8192

    const int t   = blockIdx.x;
    const int tid = threadIdx.x;
    const int tx  = tid & 63;
    const int ty  = tid >> 6;
    const int c0  = tx * 2;

    const float bi0 = g_bias[c0],       bi1 = g_bias[c0 + 1];
    const float bf0 = g_bias[128 + c0], bf1 = g_bias[128 + c0 + 1];
    const float bg0 = g_bias[256 + c0], bg1 = g_bias[256 + c0 + 1];
    const float bo0 = g_bias[384 + c0], bo1 = g_bias[384 + c0 + 1];

    int cur = 0;
    for (int k = 0; k <= 5; k++) {
        const int M = 1 << k;
        const float* Hp = Hb + (cur ^ 1) * 4096;
        const float* Cp = Cb + (cur ^ 1) * 4096;

        // Stage Z (transposed): Zs[d][m] = [x_node | h_parent]
        for (int idx = tid; idx < M * 256; idx += 512) {
            int m = idx >> 8;
            int d = idx & 255;
            float v;
            if (d < 128) v = emb[((size_t)(t * NPT + (M - 1) + m)) * D_ + d];
            else         v = (k == 0) ? 0.f : Hp[(m >> 1) * 128 + (d - 128)];
            Zs[d * SZS + m] = v;
        }
        // Prefetch W chunk 0
        {
            float* dstw = Wb;
            const float* srcw = g_Wt;
            #pragma unroll
            for (int i = 0; i < 4; i++) cpa16(dstw + (tid + i * 512) * 4, srcw + (tid + i * 512) * 4);
            CP_COMMIT();
        }
        __syncthreads();

        ull acc[4][4];
        #pragma unroll
        for (int i = 0; i < 4; i++)
            #pragma unroll
            for (int q = 0; q < 4; q++) acc[i][q] = 0ull;

        for (int c = 0; c < 16; c++) {
            CP_WAIT0();
            __syncthreads();
            if (c < 16 - 1) {
                float* dstw = Wb + ((c + 1) & 1) * 8192;
                const float* srcw = g_Wt + (c + 1) * 8192;
                #pragma unroll
                for (int i = 0; i < 4; i++) cpa16(dstw + (tid + i * 512) * 4, srcw + (tid + i * 512) * 4);
                CP_COMMIT();
            }
            const float* Ws = Wb + (c & 1) * 8192;
            #pragma unroll
            for (int kk = 0; kk < 16; kk++) {
                const float* zrow = Zs + (c * 16 + kk) * SZS + ty;
                ull a0 = dup2(zrow[0]);
                ull a1 = dup2(zrow[8]);
                ull a2 = dup2(zrow[16]);
                ull a3 = dup2(zrow[24]);
                const float* wrow = Ws + kk * 512 + c0;
                ull b0 = *(const ull*)(wrow);
                ull b1 = *(const ull*)(wrow + 128);
                ull b2 = *(const ull*)(wrow + 256);
                ull b3 = *(const ull*)(wrow + 384);
                ffma2(acc[0][0], a0, b0); ffma2(acc[0][1], a0, b1);
                ffma2(acc[0][2], a0, b2); ffma2(acc[0][3], a0, b3);
                ffma2(acc[1][0], a1, b0); ffma2(acc[1][1], a1, b1);
                ffma2(acc[1][2], a1, b2); ffma2(acc[1][3], a1, b3);
                ffma2(acc[2][0], a2, b0); ffma2(acc[2][1], a2, b1);
                ffma2(acc[2][2], a2, b2); ffma2(acc[2][3], a2, b3);
                ffma2(acc[3][0], a3, b0); ffma2(acc[3][1], a3, b1);
                ffma2(acc[3][2], a3, b2); ffma2(acc[3][3], a3, b3);
            }
        }

        // Epilogue: LSTM cell for valid rows
        float* Hc = Hb + cur * 4096;
        float* Cc = Cb + cur * 4096;
        #pragma unroll
        for (int i = 0; i < 4; i++) {
            int r = ty + i * 8;
            if (r >= M) break;
            float2 gi = unpk(acc[i][0]);
            float2 gf = unpk(acc[i][1]);
            float2 gg = unpk(acc[i][2]);
            float2 go = unpk(acc[i][3]);
            float cp0 = 0.f, cp1 = 0.f;
            if (k != 0) { cp0 = Cp[(r >> 1) * 128 + c0]; cp1 = Cp[(r >> 1) * 128 + c0 + 1]; }
            float cn0 = sigf(gf.x + bf0) * cp0 + sigf(gi.x + bi0) * tanhf_(gg.x + bg0);
            float cn1 = sigf(gf.y + bf1) * cp1 + sigf(gi.y + bi1) * tanhf_(gg.y + bg1);
            float hn0 = sigf(go.x + bo0) * tanhf_(cn0);
            float hn1 = sigf(go.y + bo1) * tanhf_(cn1);
            Cc[r * 128 + c0]     = cn0;
            Cc[r * 128 + c0 + 1] = cn1;
            Hc[r * 128 + c0]     = hn0;
            Hc[r * 128 + c0 + 1] = hn1;
        }
        __syncthreads();
        cur ^= 1;
    }

    // Write level-5 states (32 rows) to global ping-pong slot 1
    const float* Hf = Hb + (cur ^ 1) * 4096;
    const float* Cf = Cb + (cur ^ 1) * 4096;
    float* gh = g_H[1] + (size_t)(t * 32) * 128;
    float* gc = g_C[1] + (size_t)(t * 32) * 128;
    for (int idx = tid; idx < 32 * 128; idx += 512) {
        gh[idx] = Hf[idx];
        gc[idx] = Cf[idx];
    }
}

// ---------------------------------------------------------------------------
// Big levels (6..8): 256 threads, thread microtile RM rows x 4 cols/quadrant.
// tx = tid&31 -> cols c0 = 4*tx per quadrant; ty = tid>>5 -> rows ty*RM..+RM.
// W double-buffered via cp.async. 64 ffma2 per 96B smem per k-step.
// ---------------------------------------------------------------------------
template<int TM>
__global__ void __launch_bounds__(256, 1)
lstm_big_kernel(int level, int M, int dst, const float* __restrict__ emb) {
    constexpr int RM = TM / 8;          // rows per thread
    constexpr int ZS = TM + 2;          // ZS mod 32 == 2*k small -> <=2-way conflicts
    extern __shared__ float smem[];
    float* Zs = smem;                   // [256][ZS]
    float* Wb = smem + 256 * ZS;        // [2][16][512]

    const float* __restrict__ Hin  = g_H[dst ^ 1];
    const float* __restrict__ Cin  = g_C[dst ^ 1];
    float* __restrict__       Hout = g_H[dst];
    float* __restrict__       Cout = g_C[dst];

    const int tid = threadIdx.x;
    const int tx  = tid & 31;
    const int ty  = tid >> 5;
    const int m0  = blockIdx.x * TM;
    const int lmask = (1 << level) - 1;

    // Stage Z tile (transposed)
    for (int idx = tid; idx < TM * 256; idx += 256) {
        int m  = idx >> 8;
        int d  = idx & 255;
        int gm = m0 + m;
        float v = 0.f;
        if (gm < M) {
            if (d < 128) {
                int t = gm >> level;
                int j = gm & lmask;
                v = emb[((size_t)(t * NPT + lmask + j)) * D_ + d];
            } else {
                v = Hin[((size_t)(gm >> 1)) * D_ + (d - 128)];
            }
        }
        Zs[d * ZS + m] = v;
    }
    // Prefetch W chunk 0
    {
        #pragma unroll
        for (int i = 0; i < 8; i++) cpa16(Wb + (tid + i * 256) * 4, g_Wt + (tid + i * 256) * 4);
        CP_COMMIT();
    }

    ull acc[RM][4][2];
    #pragma unroll
    for (int r = 0; r < RM; r++)
        #pragma unroll
        for (int q = 0; q < 4; q++) { acc[r][q][0] = 0ull; acc[r][q][1] = 0ull; }

    __syncthreads();

    for (int c = 0; c < 16; c++) {
        CP_WAIT0();
        __syncthreads();
        if (c < 16 - 1) {
            float* dstw = Wb + ((c + 1) & 1) * 8192;
            const float* srcw = g_Wt + (c + 1) * 8192;
            #pragma unroll
            for (int i = 0; i < 8; i++) cpa16(dstw + (tid + i * 256) * 4, srcw + (tid + i * 256) * 4);
            CP_COMMIT();
        }
        const float* Ws = Wb + (c & 1) * 8192;
        #pragma unroll
        for (int kk = 0; kk < 16; kk++) {
            const float* zrow = Zs + (c * 16 + kk) * ZS + ty * RM;
            ull a[RM];
            #pragma unroll
            for (int j = 0; j < RM / 2; j++) {
                float2 z = *(const float2*)(zrow + 2 * j);
                a[2 * j]     = dup2(z.x);
                a[2 * j + 1] = dup2(z.y);
            }
            const float* wrow = Ws + kk * 512 + tx * 4;
            float4 w0 = *(const float4*)(wrow);
            float4 w1 = *(const float4*)(wrow + 128);
            float4 w2 = *(const float4*)(wrow + 256);
            float4 w3 = *(const float4*)(wrow + 384);
            ull b00 = pk2(w0.x, w0.y), b01 = pk2(w0.z, w0.w);
            ull b10 = pk2(w1.x, w1.y), b11 = pk2(w1.z, w1.w);
            ull b20 = pk2(w2.x, w2.y), b21 = pk2(w2.z, w2.w);
            ull b30 = pk2(w3.x, w3.y), b31 = pk2(w3.z, w3.w);
            #pragma unroll
            for (int r = 0; r < RM; r++) {
                ffma2(acc[r][0][0], a[r], b00); ffma2(acc[r][0][1], a[r], b01);
                ffma2(acc[r][1][0], a[r], b10); ffma2(acc[r][1][1], a[r], b11);
                ffma2(acc[r][2][0], a[r], b20); ffma2(acc[r][2][1], a[r], b21);
                ffma2(acc[r][3][0], a[r], b30); ffma2(acc[r][3][1], a[r], b31);
            }
        }
    }

    // Epilogue: bias + LSTM cell; thread owns cols c0..c0+3 per quadrant
    const int c0 = tx * 4;
    float4 bi = *(const float4*)(g_bias + c0);
    float4 bf = *(const float4*)(g_bias + 128 + c0);
    float4 bg = *(const float4*)(g_bias + 256 + c0);
    float4 bo = *(const float4*)(g_bias + 384 + c0);

    #pragma unroll
    for (int r = 0; r < RM; r++) {
        int gm = m0 + ty * RM + r;
        if (gm >= M) break;
        float2 iA = unpk(acc[r][0][0]), iB = unpk(acc[r][0][1]);
        float2 fA = unpk(acc[r][1][0]), fB = unpk(acc[r][1][1]);
        float2 gA = unpk(acc[r][2][0]), gB = unpk(acc[r][2][1]);
        float2 oA = unpk(acc[r][3][0]), oB = unpk(acc[r][3][1]);
        float4 cp = *(const float4*)(Cin + ((size_t)(gm >> 1)) * D_ + c0);

        float cn0 = sigf(fA.x + bf.x) * cp.x + sigf(iA.x + bi.x) * tanhf_(gA.x + bg.x);
        float cn1 = sigf(fA.y + bf.y) * cp.y + sigf(iA.y + bi.y) * tanhf_(gA.y + bg.y);
        float cn2 = sigf(fB.x + bf.z) * cp.z + sigf(iB.x + bi.z) * tanhf_(gB.x + bg.z);
        float cn3 = sigf(fB.y + bf.w) * cp.w + sigf(iB.y + bi.w) * tanhf_(gB.y + bg.w);
        float hn0 = sigf(oA.x + bo.x) * tanhf_(cn0);
        float hn1 = sigf(oA.y + bo.y) * tanhf_(cn1);
        float hn2 = sigf(oB.x + bo.z) * tanhf_(cn2);
        float hn3 = sigf(oB.y + bo.w) * tanhf_(cn3);

        *(float4*)(Cout + (size_t)gm * D_ + c0) = make_float4(cn0, cn1, cn2, cn3);
        *(float4*)(Hout + (size_t)gm * D_ + c0) = make_float4(hn0, hn1, hn2, hn3);
    }
}

// ---------------------------------------------------------------------------
// Gather: out[b,t,:] = active ? H_level8[t*256 + leaf, :] : 0
// ---------------------------------------------------------------------------
__global__ void gather_kernel(float4* __restrict__ out) {
    int idx = blockIdx.x * blockDim.x + threadIdx.x;
    if (idx >= BT_ * D_ / 4) return;
    int bt = idx >> 5;
    int d4 = idx & 31;
    int t  = bt % T_;
    int lf = g_leaf[bt];
    float4 v = make_float4(0.f, 0.f, 0.f, 0.f);
    if (lf >= 0)
        v = ((const float4*)&g_H[0][((size_t)(t * 256 + lf)) * D_])[d4];
    out[idx] = v;
}

// ---------------------------------------------------------------------------
// Launch
// ---------------------------------------------------------------------------
extern "C" void kernel_launch(void* const* d_in, const int* in_sizes, int n_in,
                              void* d_out, int out_size) {
    const float* cross = (const float*)d_in[0];
    const float* emb   = (const float*)d_in[1];
    const float* w_ih  = (const float*)d_in[2];
    const float* w_hh  = (const float*)d_in[3];
    const float* b_ih  = (const float*)d_in[4];
    const float* b_hh  = (const float*)d_in[5];
    // d_in[6] = paths: fixed heap layout, reconstructed analytically.
    float* out = (float*)d_out;

    const int SMEM_SMALL = (256 * SZS + 2 * 16 * 512 + 4 * 32 * 128) * 4; // 165888
    const int SMEM_B48   = (256 * 50 + 2 * 16 * 512) * 4;                 // 116736
    const int SMEM_B64   = (256 * 66 + 2 * 16 * 512) * 4;                 // 133120

    cudaFuncSetAttribute((const void*)lstm_small_kernel,
                         cudaFuncAttributeMaxDynamicSharedMemorySize, SMEM_SMALL);
    cudaFuncSetAttribute((const void*)lstm_big_kernel<48>,
                         cudaFuncAttributeMaxDynamicSharedMemorySize, SMEM_B48);
    cudaFuncSetAttribute((const void*)lstm_big_kernel<64>,
                         cudaFuncAttributeMaxDynamicSharedMemorySize, SMEM_B64);

    prep_kernel<<<512, 256>>>(w_ih, w_hh, b_ih, b_hh);
    leaf_kernel<<<BT_ * 32 / 256, 256>>>(cross);

    // Levels 0..5 fused (result in g_H[1]/g_C[1], rows t*32+j)
    lstm_small_kernel<<<T_, 512, SMEM_SMALL>>>(emb);

    // Level 6: M=6400, dst=0  (134 blocks -> 1 wave)
    lstm_big_kernel<48><<<(6400 + 47) / 48, 256, SMEM_B48>>>(6, 6400, 0, emb);
    // Level 7: M=12800, dst=1 (267 blocks -> 2 waves)
    lstm_big_kernel<48><<<(12800 + 47) / 48, 256, SMEM_B48>>>(7, 12800, 1, emb);
    // Level 8: M=25600, dst=0 (400 blocks -> 3 waves)
    lstm_big_kernel<64><<<25600 / 64, 256, SMEM_B64>>>(8, 25600, 0, emb);

    gather_kernel<<<BT_ * D_ / 4 / 256, 256>>>((float4*)out);
}